// round 1
// baseline (speedup 1.0000x reference)
#include <cuda_runtime.h>

#define HW      512
#define BATCH   16
#define CH      3
#define RSTRIP  32
#define EPS     1e-8f
#define INV_N   (1.0f / 147.0f)              // C*K*K = 3*49
#define INV_TOT (1.0f / 4194304.0f)          // B*H*W = 16*512*512

// Scratch: per pixel (vertical 7-sums): {sum_pred, sumsq_pred, sum_tgt, sumsq_tgt}
__device__ float4 g_vsum[BATCH * HW * HW];   // 67 MB static device scratch

__global__ void zero_out_kernel(float* out) { out[0] = 0.0f; }

// ---------------------------------------------------------------------------
// Pass 1: vertical 7-box of channel-summed moments. Thread = one column.
// Running prefix + 8-deep register ring (full unroll -> static indices).
// Grid: (HW/256 cols, HW/RSTRIP strips, BATCH). Block: 256.
// ---------------------------------------------------------------------------
__global__ __launch_bounds__(256)
void vpass_kernel(const float* __restrict__ pred, const float* __restrict__ tgt) {
    const int x  = blockIdx.x * 256 + threadIdx.x;
    const int r0 = blockIdx.y * RSTRIP;
    const int b  = blockIdx.z;

    const float* __restrict__ pb = pred + (size_t)b * CH * HW * HW + x;
    const float* __restrict__ tb = tgt  + (size_t)b * CH * HW * HW + x;
    float4* __restrict__ outp = g_vsum + (size_t)b * HW * HW + x;

    float Pp = 0.f, Pp2 = 0.f, Pt = 0.f, Pt2 = 0.f;
    float rp[8], rp2[8], rt[8], rt2[8];
#pragma unroll
    for (int i = 0; i < 8; ++i) { rp[i] = 0.f; rp2[i] = 0.f; rt[i] = 0.f; rt2[i] = 0.f; }

#pragma unroll
    for (int yy = 0; yy < RSTRIP + 6; ++yy) {
        const int yin = r0 - 3 + yy;
        float a0 = 0.f, a1 = 0.f, a2 = 0.f, c0 = 0.f, c1 = 0.f, c2 = 0.f;
        if ((unsigned)yin < HW) {
            const float* pr = pb + (size_t)yin * HW;
            const float* tr = tb + (size_t)yin * HW;
            a0 = pr[0]; a1 = pr[HW * HW]; a2 = pr[2 * HW * HW];
            c0 = tr[0]; c1 = tr[HW * HW]; c2 = tr[2 * HW * HW];
        }
        const float sp  = a0 + a1 + a2;
        const float sp2 = a0 * a0 + a1 * a1 + a2 * a2;
        const float st  = c0 + c1 + c2;
        const float st2 = c0 * c0 + c1 * c1 + c2 * c2;

        Pp += sp; Pp2 += sp2; Pt += st; Pt2 += st2;

        const int cur = yy & 7;
        const int old = (yy + 1) & 7;          // prefix from 7 iterations ago (0 if unwritten)
        const float vp  = Pp  - rp [old];
        const float vp2 = Pp2 - rp2[old];
        const float vt  = Pt  - rt [old];
        const float vt2 = Pt2 - rt2[old];
        rp[cur] = Pp; rp2[cur] = Pp2; rt[cur] = Pt; rt2[cur] = Pt2;

        if (yy >= 6) {
            const int r = r0 + yy - 6;
            outp[(size_t)r * HW] = make_float4(vp, vp2, vt, vt2);
        }
    }
}

// ---------------------------------------------------------------------------
// Pass 2: horizontal 7-box + std + smooth-L1 + reduction.
// Thread owns 4 consecutive pixels of one row; loads pixels [x-3, x+6] as
// 10 float4s (halo loads hit L1/L2), slides the 7-window in registers.
// Block 256 = 2 rows x 128 chunks. Grid: BATCH*HW/2 blocks.
// ---------------------------------------------------------------------------
__global__ __launch_bounds__(256)
void hpass_kernel(float* __restrict__ out) {
    const int chunk    = threadIdx.x & 127;
    const int rowInBlk = threadIdx.x >> 7;
    const int rowG     = blockIdx.x * 2 + rowInBlk;       // = b*512 + y
    const float4* __restrict__ rowptr = g_vsum + (size_t)rowG * HW;
    const int xbase = chunk * 4;

    float4 w[10];
#pragma unroll
    for (int i = 0; i < 10; ++i) {
        const int xi = xbase - 3 + i;
        if ((unsigned)xi < HW) w[i] = rowptr[xi];
        else                   w[i] = make_float4(0.f, 0.f, 0.f, 0.f);
    }

    float4 s;
    s.x = w[0].x + w[1].x + w[2].x + w[3].x + w[4].x + w[5].x + w[6].x;
    s.y = w[0].y + w[1].y + w[2].y + w[3].y + w[4].y + w[5].y + w[6].y;
    s.z = w[0].z + w[1].z + w[2].z + w[3].z + w[4].z + w[5].z + w[6].z;
    s.w = w[0].w + w[1].w + w[2].w + w[3].w + w[4].w + w[5].w + w[6].w;

    float acc = 0.f;
#pragma unroll
    for (int j = 0; j < 4; ++j) {
        const float mup  = s.x * INV_N;
        const float varp = fmaf(-mup, mup, s.y * INV_N);
        const float stdp = sqrtf(varp + EPS);
        const float mut  = s.z * INV_N;
        const float vart = fmaf(-mut, mut, s.w * INV_N);
        const float stdt = sqrtf(vart + EPS);
        const float d  = stdp - stdt;
        const float ad = fabsf(d);
        acc += (ad < 1.f) ? 0.5f * d * d : (ad - 0.5f);
        if (j < 3) {
            s.x += w[j + 7].x - w[j].x;
            s.y += w[j + 7].y - w[j].y;
            s.z += w[j + 7].z - w[j].z;
            s.w += w[j + 7].w - w[j].w;
        }
    }

    // warp reduce
#pragma unroll
    for (int o = 16; o > 0; o >>= 1) acc += __shfl_xor_sync(0xFFFFFFFFu, acc, o);

    __shared__ float ws[8];
    if ((threadIdx.x & 31) == 0) ws[threadIdx.x >> 5] = acc;
    __syncthreads();
    if (threadIdx.x == 0) {
        float bs = 0.f;
#pragma unroll
        for (int i = 0; i < 8; ++i) bs += ws[i];
        atomicAdd(out, bs * INV_TOT);
    }
}

extern "C" void kernel_launch(void* const* d_in, const int* in_sizes, int n_in,
                              void* d_out, int out_size) {
    const float* pred = (const float*)d_in[0];
    const float* tgt  = (const float*)d_in[1];
    float* out = (float*)d_out;
    (void)in_sizes; (void)n_in; (void)out_size;

    zero_out_kernel<<<1, 1>>>(out);

    dim3 vgrid(HW / 256, HW / RSTRIP, BATCH);   // (2, 16, 16) = 512 blocks
    vpass_kernel<<<vgrid, 256>>>(pred, tgt);

    hpass_kernel<<<BATCH * HW / 2, 256>>>(out); // 4096 blocks
}

// round 2
// speedup vs baseline: 1.6000x; 1.6000x over previous
#include <cuda_runtime.h>

#define HW      512
#define BATCH   16
#define STRIP   32                 // output rows per block
#define NB      8                  // batches per block
#define BR      4                  // rows per batch
#define EPS     1e-8f
#define INV_N   (1.0f / 147.0f)            // C*K*K = 3*49
#define INV_TOT (1.0f / 4194304.0f)        // B*H*W
#define CHS     262144             // HW*HW

// pad-swizzle: one dummy float4 every 8 to break stride-64B bank conflicts
#define SIDX(x) ((x) + ((x) >> 3))
// max unpadded index 517 -> SIDX = 581 -> round to 584

__global__ void zero_out_kernel(float* out) { out[0] = 0.0f; }

__device__ __forceinline__ float px_loss(float sx, float sy, float sz, float sw) {
    const float mup  = sx * INV_N;
    const float varp = fmaf(-mup, mup, sy * INV_N);
    const float stdp = sqrtf(varp + EPS);
    const float mut  = sz * INV_N;
    const float vart = fmaf(-mut, mut, sw * INV_N);
    const float stdt = sqrtf(vart + EPS);
    const float d  = stdp - stdt;
    const float ad = fabsf(d);
    return (ad < 1.0f) ? 0.5f * d * d : (ad - 0.5f);
}

__global__ __launch_bounds__(512)
void fused_kernel(const float* __restrict__ pred, const float* __restrict__ tgt,
                  float* __restrict__ out) {
    __shared__ float4 buf[BR][584];
    __shared__ float  wred[16];

    const int tid = threadIdx.x;
    const int r0  = blockIdx.x * STRIP;          // strip start row
    const int b   = blockIdx.y;                  // image index

    const float* __restrict__ pb = pred + (size_t)b * 3 * CHS + tid;
    const float* __restrict__ tb = tgt  + (size_t)b * 3 * CHS + tid;

    // vertical prefix state (per column = per thread)
    float Pp = 0.f, Pp2 = 0.f, Pt = 0.f, Pt2 = 0.f;
    float rgP[8], rgP2[8], rgT[8], rgT2[8];
#pragma unroll
    for (int i = 0; i < 8; ++i) { rgP[i] = 0.f; rgP2[i] = 0.f; rgT[i] = 0.f; rgT2[i] = 0.f; }

    // ---- warm-up: rows i = 0..5  (yin = r0-3+i), prefixes only ----
#pragma unroll
    for (int i = 0; i < 6; ++i) {
        const int yin = r0 - 3 + i;
        float a0 = 0.f, a1 = 0.f, a2 = 0.f, c0 = 0.f, c1 = 0.f, c2 = 0.f;
        if ((unsigned)yin < HW) {
            const float* pr = pb + (size_t)yin * HW;
            const float* tr = tb + (size_t)yin * HW;
            a0 = pr[0]; a1 = pr[CHS]; a2 = pr[2 * CHS];
            c0 = tr[0]; c1 = tr[CHS]; c2 = tr[2 * CHS];
        }
        Pp  += a0 + a1 + a2;
        Pp2 += a0 * a0 + a1 * a1 + a2 * a2;
        Pt  += c0 + c1 + c2;
        Pt2 += c0 * c0 + c1 * c1 + c2 * c2;
        rgP[i] = Pp; rgP2[i] = Pp2; rgT[i] = Pt; rgT2[i] = Pt2;
    }

    // ---- preload batch 0: rows i = 6..9 -> vcur ----
    float4 vcur[BR];
#pragma unroll
    for (int r = 0; r < BR; ++r) {
        const int i   = 6 + r;
        const int yin = r0 + 3 + r;
        float a0 = 0.f, a1 = 0.f, a2 = 0.f, c0 = 0.f, c1 = 0.f, c2 = 0.f;
        if ((unsigned)yin < HW) {
            const float* pr = pb + (size_t)yin * HW;
            const float* tr = tb + (size_t)yin * HW;
            a0 = pr[0]; a1 = pr[CHS]; a2 = pr[2 * CHS];
            c0 = tr[0]; c1 = tr[CHS]; c2 = tr[2 * CHS];
        }
        Pp  += a0 + a1 + a2;
        Pp2 += a0 * a0 + a1 * a1 + a2 * a2;
        Pt  += c0 + c1 + c2;
        Pt2 += c0 * c0 + c1 * c1 + c2 * c2;
        vcur[r].x = Pp  - rgP [(i + 1) & 7];
        vcur[r].y = Pp2 - rgP2[(i + 1) & 7];
        vcur[r].z = Pt  - rgT [(i + 1) & 7];
        vcur[r].w = Pt2 - rgT2[(i + 1) & 7];
        rgP[i & 7] = Pp; rgP2[i & 7] = Pp2; rgT[i & 7] = Pt; rgT2[i & 7] = Pt2;
    }

    float acc = 0.f;
    const int rr = tid >> 7;             // compute-phase row 0..3
    const int xb = (tid & 127) * 4;      // compute-phase window base

    // ---- main loop: 8 batches of 4 rows, fully unrolled ----
#pragma unroll
    for (int bb = 0; bb < NB; ++bb) {
        // stage vcur into smem (column tid -> unpadded idx tid+3)
#pragma unroll
        for (int r = 0; r < BR; ++r) buf[r][SIDX(tid + 3)] = vcur[r];
        if (tid < 3) {
#pragma unroll
            for (int r = 0; r < BR; ++r) buf[r][SIDX(tid)] = make_float4(0.f, 0.f, 0.f, 0.f);
        }
        if (tid >= 509) {
#pragma unroll
            for (int r = 0; r < BR; ++r) buf[r][SIDX(tid + 6)] = make_float4(0.f, 0.f, 0.f, 0.f);
        }
        __syncthreads();

        // issue next batch's loads early (rows i = 10+4bb+r) — overlap with compute
        float a0[BR], a1[BR], a2[BR], c0[BR], c1[BR], c2[BR];
        if (bb < NB - 1) {
#pragma unroll
            for (int r = 0; r < BR; ++r) {
                const int yin = r0 + 7 + 4 * bb + r;
                const bool ok = (unsigned)yin < HW;
                const float* pr = pb + (size_t)yin * HW;
                const float* tr = tb + (size_t)yin * HW;
                a0[r] = ok ? pr[0]       : 0.f;
                a1[r] = ok ? pr[CHS]     : 0.f;
                a2[r] = ok ? pr[2 * CHS] : 0.f;
                c0[r] = ok ? tr[0]       : 0.f;
                c1[r] = ok ? tr[CHS]     : 0.f;
                c2[r] = ok ? tr[2 * CHS] : 0.f;
            }
        }

        // horizontal 7-box + loss for this batch (register slide over 4 px)
        {
            float4 w0 = buf[rr][SIDX(xb + 0)];
            float4 w1 = buf[rr][SIDX(xb + 1)];
            float4 w2 = buf[rr][SIDX(xb + 2)];
            float4 w3 = buf[rr][SIDX(xb + 3)];
            float4 w4 = buf[rr][SIDX(xb + 4)];
            float4 w5 = buf[rr][SIDX(xb + 5)];
            float4 w6 = buf[rr][SIDX(xb + 6)];
            float sx = w0.x + w1.x + w2.x + w3.x + w4.x + w5.x + w6.x;
            float sy = w0.y + w1.y + w2.y + w3.y + w4.y + w5.y + w6.y;
            float sz = w0.z + w1.z + w2.z + w3.z + w4.z + w5.z + w6.z;
            float sw = w0.w + w1.w + w2.w + w3.w + w4.w + w5.w + w6.w;
            acc += px_loss(sx, sy, sz, sw);

            float4 w7 = buf[rr][SIDX(xb + 7)];
            sx += w7.x - w0.x; sy += w7.y - w0.y; sz += w7.z - w0.z; sw += w7.w - w0.w;
            acc += px_loss(sx, sy, sz, sw);

            float4 w8 = buf[rr][SIDX(xb + 8)];
            sx += w8.x - w1.x; sy += w8.y - w1.y; sz += w8.z - w1.z; sw += w8.w - w1.w;
            acc += px_loss(sx, sy, sz, sw);

            float4 w9 = buf[rr][SIDX(xb + 9)];
            sx += w9.x - w2.x; sy += w9.y - w2.y; sz += w9.z - w2.z; sw += w9.w - w2.w;
            acc += px_loss(sx, sy, sz, sw);
        }
        __syncthreads();

        // consume prefetched rows -> vcur for next batch
        if (bb < NB - 1) {
#pragma unroll
            for (int r = 0; r < BR; ++r) {
                const int i = 10 + 4 * bb + r;
                Pp  += a0[r] + a1[r] + a2[r];
                Pp2 += a0[r] * a0[r] + a1[r] * a1[r] + a2[r] * a2[r];
                Pt  += c0[r] + c1[r] + c2[r];
                Pt2 += c0[r] * c0[r] + c1[r] * c1[r] + c2[r] * c2[r];
                vcur[r].x = Pp  - rgP [(i + 1) & 7];
                vcur[r].y = Pp2 - rgP2[(i + 1) & 7];
                vcur[r].z = Pt  - rgT [(i + 1) & 7];
                vcur[r].w = Pt2 - rgT2[(i + 1) & 7];
                rgP[i & 7] = Pp; rgP2[i & 7] = Pp2; rgT[i & 7] = Pt; rgT2[i & 7] = Pt2;
            }
        }
    }

    // ---- reduction ----
#pragma unroll
    for (int o = 16; o > 0; o >>= 1) acc += __shfl_xor_sync(0xFFFFFFFFu, acc, o);
    if ((tid & 31) == 0) wred[tid >> 5] = acc;
    __syncthreads();
    if (tid == 0) {
        float bs = 0.f;
#pragma unroll
        for (int i = 0; i < 16; ++i) bs += wred[i];
        atomicAdd(out, bs * INV_TOT);
    }
}

extern "C" void kernel_launch(void* const* d_in, const int* in_sizes, int n_in,
                              void* d_out, int out_size) {
    const float* pred = (const float*)d_in[0];
    const float* tgt  = (const float*)d_in[1];
    float* out = (float*)d_out;
    (void)in_sizes; (void)n_in; (void)out_size;

    zero_out_kernel<<<1, 1>>>(out);

    dim3 grid(HW / STRIP, BATCH);    // (16, 16) = 256 blocks
    fused_kernel<<<grid, 512>>>(pred, tgt, out);
}

// round 5
// speedup vs baseline: 1.9282x; 1.2051x over previous
#include <cuda_runtime.h>

#define HW      512
#define CHS     (HW * HW)
#define BATCH   16
#define STRIP   32
#define EPS     1e-8f
#define INV_N   (1.0f / 147.0f)            // C*K*K = 3*49
#define INV_TOT (1.0f / 4194304.0f)        // B*H*W

// pad-swizzle for the horizontal buffer (breaks stride-64B conflicts)
#define SIDX(x) ((x) + ((x) >> 3))

#define RING_F4  (7 * 512)                  // 7-slot ring of row moments
#define BUF_W    582                        // SIDX(517)+1
#define BUF_F4   (4 * BUF_W)
#define SMEM_BYTES ((RING_F4 + BUF_F4) * 16 + 64)

__global__ void zero_out_kernel(float* out) { out[0] = 0.0f; }

__device__ __forceinline__ float px_loss(float sx, float sy, float sz, float sw) {
    const float mup  = sx * INV_N;
    const float varp = fmaf(-mup, mup, sy * INV_N);
    const float stdp = sqrtf(varp + EPS);
    const float mut  = sz * INV_N;
    const float vart = fmaf(-mut, mut, sw * INV_N);
    const float stdt = sqrtf(vart + EPS);
    const float d  = stdp - stdt;
    const float ad = fabsf(d);
    return (ad < 1.0f) ? 0.5f * d * d : (ad - 0.5f);
}

__global__ __launch_bounds__(512, 2)
void fused_kernel(const float* __restrict__ pred, const float* __restrict__ tgt,
                  float* __restrict__ out) {
    extern __shared__ float4 smem[];
    float4* ring = smem;                       // [7][512]
    float4* buf  = smem + RING_F4;             // [4][BUF_W]
    float*  wred = (float*)(smem + RING_F4 + BUF_F4);

    const int tid = threadIdx.x;
    const int r0  = blockIdx.x * STRIP;
    const int b   = blockIdx.y;

    const float* __restrict__ pb = pred + (size_t)b * 3 * CHS + tid;
    const float* __restrict__ tb = tgt  + (size_t)b * 3 * CHS + tid;

    // always-zero horizontal-halo entries (cols -3..-1 and 512..514), written once
    if (tid < 3) {
#pragma unroll
        for (int r = 0; r < 4; ++r) {
            buf[r * BUF_W + SIDX(tid)]       = make_float4(0.f, 0.f, 0.f, 0.f);
            buf[r * BUF_W + SIDX(515 + tid)] = make_float4(0.f, 0.f, 0.f, 0.f);
        }
    }

    // running vertical 7-sum of row moments for this column
    float Vx = 0.f, Vy = 0.f, Vz = 0.f, Vw = 0.f;

    // ---- pre-loop: rows i = 0..9 (yin = r0-3+i); fills ring, writes batch-0 buf ----
#pragma unroll
    for (int i = 0; i < 10; ++i) {
        const int yin = r0 - 3 + i;
        const bool ok = (unsigned)yin < HW;
        const float* pr = pb + yin * HW;
        const float* tr = tb + yin * HW;
        const float a0 = ok ? pr[0]       : 0.f;
        const float a1 = ok ? pr[CHS]     : 0.f;
        const float a2 = ok ? pr[2 * CHS] : 0.f;
        const float c0 = ok ? tr[0]       : 0.f;
        const float c1 = ok ? tr[CHS]     : 0.f;
        const float c2 = ok ? tr[2 * CHS] : 0.f;
        float4 m;
        m.x = a0 + a1 + a2;
        m.y = a0 * a0 + a1 * a1 + a2 * a2;
        m.z = c0 + c1 + c2;
        m.w = c0 * c0 + c1 * c1 + c2 * c2;
        const int slot = (i % 7) * 512 + tid;
        if (i >= 7) {
            const float4 mo = ring[slot];      // moment from 7 rows ago (same slot)
            Vx += m.x - mo.x; Vy += m.y - mo.y; Vz += m.z - mo.z; Vw += m.w - mo.w;
        } else {
            Vx += m.x; Vy += m.y; Vz += m.z; Vw += m.w;
        }
        ring[slot] = m;
        if (i >= 6) buf[(i - 6) * BUF_W + SIDX(tid + 3)] = make_float4(Vx, Vy, Vz, Vw);
    }

    float acc = 0.f;
    const int rr = tid >> 7;                 // horizontal-phase row 0..3
    const int xb = (tid & 127) * 4;          // horizontal-phase window base
    const float4* brow = buf + rr * BUF_W;

    // ---- main loop: 8 batches of 4 rows ----
#pragma unroll
    for (int bb = 0; bb < 8; ++bb) {
        __syncthreads();                     // buf for batch bb fully written

        // issue next batch's global loads first so they fly during compute
        float A[4][6];
        if (bb < 7) {
#pragma unroll
            for (int r = 0; r < 4; ++r) {
                const int yin = r0 + 7 + 4 * bb + r;
                const bool ok = (unsigned)yin < HW;
                const float* pr = pb + yin * HW;
                const float* tr = tb + yin * HW;
                A[r][0] = ok ? pr[0]       : 0.f;
                A[r][1] = ok ? pr[CHS]     : 0.f;
                A[r][2] = ok ? pr[2 * CHS] : 0.f;
                A[r][3] = ok ? tr[0]       : 0.f;
                A[r][4] = ok ? tr[CHS]     : 0.f;
                A[r][5] = ok ? tr[2 * CHS] : 0.f;
            }
        }

        // horizontal 7-box + loss (register slide over this thread's 4 pixels)
        {
            const float4 w0 = brow[SIDX(xb + 0)];
            const float4 w1 = brow[SIDX(xb + 1)];
            const float4 w2 = brow[SIDX(xb + 2)];
            const float4 w3 = brow[SIDX(xb + 3)];
            const float4 w4 = brow[SIDX(xb + 4)];
            const float4 w5 = brow[SIDX(xb + 5)];
            const float4 w6 = brow[SIDX(xb + 6)];
            float sx = w0.x + w1.x + w2.x + w3.x + w4.x + w5.x + w6.x;
            float sy = w0.y + w1.y + w2.y + w3.y + w4.y + w5.y + w6.y;
            float sz = w0.z + w1.z + w2.z + w3.z + w4.z + w5.z + w6.z;
            float sw = w0.w + w1.w + w2.w + w3.w + w4.w + w5.w + w6.w;
            acc += px_loss(sx, sy, sz, sw);

            const float4 w7 = brow[SIDX(xb + 7)];
            sx += w7.x - w0.x; sy += w7.y - w0.y; sz += w7.z - w0.z; sw += w7.w - w0.w;
            acc += px_loss(sx, sy, sz, sw);

            const float4 w8 = brow[SIDX(xb + 8)];
            sx += w8.x - w1.x; sy += w8.y - w1.y; sz += w8.z - w1.z; sw += w8.w - w1.w;
            acc += px_loss(sx, sy, sz, sw);

            const float4 w9 = brow[SIDX(xb + 9)];
            sx += w9.x - w2.x; sy += w9.y - w2.y; sz += w9.z - w2.z; sw += w9.w - w2.w;
            acc += px_loss(sx, sy, sz, sw);
        }

        __syncthreads();                     // all buf reads for batch bb complete

        // fold prefetched rows: update V via smem ring, write next batch's buf rows
        if (bb < 7) {
#pragma unroll
            for (int r = 0; r < 4; ++r) {
                const int i = 10 + 4 * bb + r;
                float4 m;
                m.x = A[r][0] + A[r][1] + A[r][2];
                m.y = A[r][0] * A[r][0] + A[r][1] * A[r][1] + A[r][2] * A[r][2];
                m.z = A[r][3] + A[r][4] + A[r][5];
                m.w = A[r][3] * A[r][3] + A[r][4] * A[r][4] + A[r][5] * A[r][5];
                const int slot = (i % 7) * 512 + tid;
                const float4 mo = ring[slot];
                Vx += m.x - mo.x; Vy += m.y - mo.y; Vz += m.z - mo.z; Vw += m.w - mo.w;
                ring[slot] = m;
                buf[r * BUF_W + SIDX(tid + 3)] = make_float4(Vx, Vy, Vz, Vw);
            }
        }
    }

    // ---- reduction ----
#pragma unroll
    for (int o = 16; o > 0; o >>= 1) acc += __shfl_xor_sync(0xFFFFFFFFu, acc, o);
    if ((tid & 31) == 0) wred[tid >> 5] = acc;
    __syncthreads();
    if (tid == 0) {
        float bs = 0.f;
#pragma unroll
        for (int i = 0; i < 16; ++i) bs += wred[i];
        atomicAdd(out, bs * INV_TOT);
    }
}

extern "C" void kernel_launch(void* const* d_in, const int* in_sizes, int n_in,
                              void* d_out, int out_size) {
    const float* pred = (const float*)d_in[0];
    const float* tgt  = (const float*)d_in[1];
    float* out = (float*)d_out;
    (void)in_sizes; (void)n_in; (void)out_size;

    cudaFuncSetAttribute(fused_kernel, cudaFuncAttributeMaxDynamicSharedMemorySize,
                         SMEM_BYTES);

    zero_out_kernel<<<1, 1>>>(out);

    dim3 grid(HW / STRIP, BATCH);            // (16, 16) = 256 blocks
    fused_kernel<<<grid, 512, SMEM_BYTES>>>(pred, tgt, out);
}